// round 16
// baseline (speedup 1.0000x reference)
#include <cuda_runtime.h>
#include <mma.h>
#include <cuda_fp16.h>
#include <math.h>
#include <stdint.h>
#include <string.h>

using namespace nvcuda;

// Problem constants
#define BB 8
#define SS 1024
#define DD 512
#define HH 8
#define HD 64
#define S2 (SS/2)

// ---------------- scratch (static device globals; no cudaMalloc) -------------
__device__ __half g_qkvh [(size_t)BB*SS*3*DD];
__device__ __half g_attnh[(size_t)BB*SS*DD];
__device__ __half g_hh   [(size_t)BB*SS*4*DD];
__device__ __half g_xh   [(size_t)BB*SS*DD];
__device__ __half g_pooledh[(size_t)BB*S2*DD];
__device__ __half g_x2h  [(size_t)BB*SS*DD];
__device__ __half g_w1h  [1536*512];
__device__ __half g_wo1h [512*512];
__device__ __half g_w2h  [1536*512];
__device__ __half g_wo2h [512*512];
__device__ __half g_wf1h [2048*512];
__device__ __half g_wf2h [512*2048];

__device__ float g_x1    [(size_t)BB*SS*DD];
__device__ float g_a2    [(size_t)BB*S2*DD];
__device__ float g_x2    [(size_t)BB*SS*DD];
__device__ float g_ff    [(size_t)BB*SS*DD];

// ---------------- helpers -----------------------------------------------------
__device__ __forceinline__ uint32_t h2_u32(__half2 h)
{
    uint32_t u;
    memcpy(&u, &h, 4);
    return u;
}
__device__ __forceinline__ void cp16h(__half* dst, const __half* src)
{
    unsigned sa = (unsigned)__cvta_generic_to_shared(dst);
    asm volatile("cp.async.cg.shared.global [%0], [%1], 16;\n" :: "r"(sa), "l"(src));
}
__device__ __forceinline__ void cp_commit()
{
    asm volatile("cp.async.commit_group;\n");
}

// ---------------- fp32 -> fp16 conversion ------------------------------------
__global__ void f2h_k(const float* __restrict__ in, __half* __restrict__ out)
{
    size_t i = ((size_t)blockIdx.x * 256 + threadIdx.x) * 4;
    float4 v = *(const float4*)(in + i);
    uint2 hv;
    hv.x = h2_u32(__floats2half2_rn(v.x, v.y));
    hv.y = h2_u32(__floats2half2_rn(v.z, v.w));
    *(uint2*)(out + i) = hv;
}

// =====================================================================
// NT fp16 GEMM: C[m,n] = A[m,k] * B[n,k]  (+bias, opt GELU)
// BK=64 (4 k16 steps/stage), cp.async double-buffered, 128x128 block,
// 8 warps, 2 CTAs/SM.  ACT: 0/1/2.  OUTH: 1 -> fp16 output.
// smem: 2 stages x (A 128x72h + B 128x72h) = 73728 B; epilogue reuses 67584 B.
// =====================================================================
#define GE_SMEM 73728
#define HP 72
#define HSTG (2*128*HP)    // halfs per stage (A + B)

template<int ACT, int OUTH>
__global__ __launch_bounds__(256, 2)
void gemm_h(const __half* __restrict__ A, int ldA,
            const __half* __restrict__ B, int ldB,
            const float* __restrict__ bias,
            void* __restrict__ Cv, int ldC, int K)
{
    constexpr int BM = 128, BN = 128;
    constexpr int WARPS_M = 2;
    constexpr int TM = 4, TN = 2;
    constexpr int NTH = 256;

    extern __shared__ __align__(128) char smem[];
    __half* hs = (__half*)smem;

    const int tid = threadIdx.x;
    const int wid = tid >> 5;
    const int warp_m = wid % WARPS_M;
    const int warp_n = wid / WARPS_M;
    const int m0 = blockIdx.y * BM;
    const int n0 = blockIdx.x * BN;

    wmma::fragment<wmma::accumulator, 16, 16, 16, float> acc[TM][TN];
#pragma unroll
    for (int i = 0; i < TM; i++)
#pragma unroll
        for (int j = 0; j < TN; j++) wmma::fill_fragment(acc[i][j], 0.0f);

    const int nt = K >> 6;

    // loader: A and B tiles 128 rows x 64 halfs (8 chunks of 8 halfs per row)
    auto load_stage = [&](int st, int k0) {
        __half* as = hs + st * HSTG;
        __half* bs = as + 128 * HP;
#pragma unroll
        for (int q = 0; q < 4; q++) {
            int ch = tid + q * NTH;       // 0..1023
            int r = ch >> 3;
            int c = (ch & 7) * 8;
            cp16h(as + r * HP + c, A + (size_t)(m0 + r) * ldA + k0 + c);
        }
#pragma unroll
        for (int q = 0; q < 4; q++) {
            int ch = tid + q * NTH;
            int r = ch >> 3;
            int c = (ch & 7) * 8;
            cp16h(bs + r * HP + c, B + (size_t)(n0 + r) * ldB + k0 + c);
        }
        cp_commit();
    };

    load_stage(0, 0);

    for (int it = 0; it < nt; it++) {
        const int cur = it & 1;
        if (it + 1 < nt) {
            load_stage(cur ^ 1, (it + 1) << 6);
            asm volatile("cp.async.wait_group 1;\n");
        } else {
            asm volatile("cp.async.wait_group 0;\n");
        }
        __syncthreads();

        const __half* as = hs + cur * HSTG;
        const __half* bs = as + 128 * HP;
#pragma unroll
        for (int ks = 0; ks < 4; ks++) {
            const int kk = ks * 16;
            wmma::fragment<wmma::matrix_a, 16, 16, 16, __half, wmma::row_major> af[TM];
            wmma::fragment<wmma::matrix_b, 16, 16, 16, __half, wmma::col_major> bf[TN];
#pragma unroll
            for (int i = 0; i < TM; i++)
                wmma::load_matrix_sync(af[i],
                    as + (warp_m * TM * 16 + i * 16) * HP + kk, HP);
#pragma unroll
            for (int j = 0; j < TN; j++)
                wmma::load_matrix_sync(bf[j],
                    bs + (warp_n * TN * 16 + j * 16) * HP + kk, HP);
#pragma unroll
            for (int i = 0; i < TM; i++)
#pragma unroll
                for (int j = 0; j < TN; j++)
                    wmma::mma_sync(acc[i][j], af[i], bf[j], acc[i][j]);
        }
        __syncthreads();
    }

    // ---- epilogue via smem staging ----
    constexpr int CSTR = BN + 4;
    float* St = (float*)smem;
#pragma unroll
    for (int i = 0; i < TM; i++)
#pragma unroll
        for (int j = 0; j < TN; j++)
            wmma::store_matrix_sync(
                St + (warp_m * TM * 16 + i * 16) * CSTR + warp_n * TN * 16 + j * 16,
                acc[i][j], CSTR, wmma::mem_row_major);
    __syncthreads();

#pragma unroll
    for (int idx = tid; idx < BM * BN / 4; idx += NTH) {
        int r = idx >> 5;
        int c = (idx & 31) * 4;
        float4 v = *(float4*)&St[r * CSTR + c];
        if (ACT >= 1) {
            float4 bv = *(const float4*)&bias[n0 + c];
            v.x += bv.x; v.y += bv.y; v.z += bv.z; v.w += bv.w;
        }
        if (ACT == 2) {
            v.x = 0.5f * v.x * (1.0f + erff(v.x * 0.70710678118654752f));
            v.y = 0.5f * v.y * (1.0f + erff(v.y * 0.70710678118654752f));
            v.z = 0.5f * v.z * (1.0f + erff(v.z * 0.70710678118654752f));
            v.w = 0.5f * v.w * (1.0f + erff(v.w * 0.70710678118654752f));
        }
        if (OUTH) {
            __half* Ch = (__half*)Cv;
            uint2 hv;
            hv.x = h2_u32(__floats2half2_rn(v.x, v.y));
            hv.y = h2_u32(__floats2half2_rn(v.z, v.w));
            *(uint2*)&Ch[(size_t)(m0 + r) * ldC + n0 + c] = hv;
        } else {
            float* Cf = (float*)Cv;
            *(float4*)&Cf[(size_t)(m0 + r) * ldC + n0 + c] = v;
        }
    }
}

// =====================================================================
// Flash attention fp16: BQ=128, double-buffered KV, fp32 softmax/O.
// smem: Q(128x72h) + 2x[K,V](64x72h) + P(128x72h) + S(128x68f) = 108544 B
// -> 2 CTAs/SM.
// =====================================================================
#define FH_P 72
#define FH_SP 68
#define FH_KVT (64 * FH_P)
#define FH_SMEM ((128*FH_P + 4*FH_KVT + 128*FH_P) * 2 + 128*FH_SP*4)

template<int SQ>
__global__ __launch_bounds__(256, 2)
void flash_fp16(const __half* __restrict__ qkv, __half* __restrict__ attn)
{
    extern __shared__ __align__(128) char smem[];
    __half* Qs = (__half*)smem;                 // 128 x 72
    __half* KV = Qs + 128 * FH_P;               // [2 stages][K,V] 64x72 each
    __half* Ps = KV + 4 * FH_KVT;               // 128 x 72
    float*  Ss = (float*)(Ps + 128 * FH_P);     // 128 x 68

    const int z = blockIdx.z;
    const int bb = z >> 3, hh = z & 7;
    const int q0 = blockIdx.y * 128;
    const __half* Qg = qkv + (size_t)bb * SQ * 1536 + hh * 64;
    const __half* Kg = Qg + 512;
    const __half* Vg = Qg + 1024;

    const int tid = threadIdx.x;
    const int wid = tid >> 5;
    const int warp_m = wid & 3;
    const int warp_n = wid >> 2;

    const int row = tid >> 1;
    const int cbase = (tid & 1) * 32;

    // ---- stage Q + KV stage 0 ----
#pragma unroll
    for (int i = tid; i < 128 * 8; i += 256) {
        int r = i >> 3;
        int c = (i & 7) * 8;
        cp16h(Qs + r * FH_P + c, Qg + (size_t)(q0 + r) * 1536 + c);
    }
#pragma unroll
    for (int i = tid; i < 64 * 8; i += 256) {
        int r = i >> 3;
        int c = (i & 7) * 8;
        cp16h(KV + r * FH_P + c,          Kg + (size_t)r * 1536 + c);
        cp16h(KV + FH_KVT + r * FH_P + c, Vg + (size_t)r * 1536 + c);
    }
    cp_commit();

    float m_run = -1e30f, l_run = 0.0f;
    float O[32];
#pragma unroll
    for (int c = 0; c < 32; c++) O[c] = 0.0f;

    const int NT = SQ / 64;
    for (int kt = 0; kt < NT; kt++) {
        const int cur = kt & 1;
        if (kt + 1 < NT) {
            const int t0 = (kt + 1) * 64;
            __half* kn = KV + (cur ^ 1) * 2 * FH_KVT;
#pragma unroll
            for (int i = tid; i < 64 * 8; i += 256) {
                int r = i >> 3;
                int c = (i & 7) * 8;
                cp16h(kn + r * FH_P + c,          Kg + (size_t)(t0 + r) * 1536 + c);
                cp16h(kn + FH_KVT + r * FH_P + c, Vg + (size_t)(t0 + r) * 1536 + c);
            }
            cp_commit();
            asm volatile("cp.async.wait_group 1;\n");
        } else {
            asm volatile("cp.async.wait_group 0;\n");
        }
        __syncthreads();   // KV cur ready; orders prev merge-reads before S store

        const __half* Ks = KV + cur * 2 * FH_KVT;
        const __half* Vs = Ks + FH_KVT;

        // ---- S = Q K^T ----
        wmma::fragment<wmma::accumulator, 16, 16, 16, float> sacc[2][2];
#pragma unroll
        for (int i = 0; i < 2; i++)
#pragma unroll
            for (int j = 0; j < 2; j++) wmma::fill_fragment(sacc[i][j], 0.0f);
#pragma unroll
        for (int ks = 0; ks < 4; ks++) {
            const int kk = ks * 16;
            wmma::fragment<wmma::matrix_a, 16, 16, 16, __half, wmma::row_major> af[2];
            wmma::fragment<wmma::matrix_b, 16, 16, 16, __half, wmma::col_major> bf[2];
#pragma unroll
            for (int i = 0; i < 2; i++)
                wmma::load_matrix_sync(af[i],
                    Qs + (warp_m * 32 + i * 16) * FH_P + kk, FH_P);
#pragma unroll
            for (int j = 0; j < 2; j++)
                wmma::load_matrix_sync(bf[j],
                    Ks + (warp_n * 32 + j * 16) * FH_P + kk, FH_P);
#pragma unroll
            for (int i = 0; i < 2; i++)
#pragma unroll
                for (int j = 0; j < 2; j++)
                    wmma::mma_sync(sacc[i][j], af[i], bf[j], sacc[i][j]);
        }
#pragma unroll
        for (int i = 0; i < 2; i++)
#pragma unroll
            for (int j = 0; j < 2; j++) {
#pragma unroll
                for (int t = 0; t < sacc[i][j].num_elements; t++)
                    sacc[i][j].x[t] *= 0.125f;
                wmma::store_matrix_sync(
                    Ss + (warp_m * 32 + i * 16) * FH_SP + warp_n * 32 + j * 16,
                    sacc[i][j], FH_SP, wmma::mem_row_major);
            }
        __syncthreads();   // S complete

        // ---- online softmax: Ss (fp32) -> Ps (fp16) ----
        float* rp = Ss + row * FH_SP + cbase;
        __half* pp = Ps + row * FH_P + cbase;
        float mx = -1e30f;
#pragma unroll
        for (int c = 0; c < 32; c++) mx = fmaxf(mx, rp[c]);
        mx = fmaxf(mx, __shfl_xor_sync(~0u, mx, 1));
        float m_new = fmaxf(m_run, mx);
        float alpha = __expf(m_run - m_new);
        float sum = 0.0f;
#pragma unroll
        for (int c = 0; c < 32; c += 2) {
            float p0 = __expf(rp[c + 0] - m_new);
            float p1 = __expf(rp[c + 1] - m_new);
            sum += p0 + p1;
            *(__half2*)(pp + c) = __floats2half2_rn(p0, p1);
        }
        sum += __shfl_xor_sync(~0u, sum, 1);
        l_run = l_run * alpha + sum;
        m_run = m_new;
        __syncthreads();   // P ready

        // ---- PV = P @ V ----
        wmma::fragment<wmma::accumulator, 16, 16, 16, float> oacc[2][2];
#pragma unroll
        for (int i = 0; i < 2; i++)
#pragma unroll
            for (int j = 0; j < 2; j++) wmma::fill_fragment(oacc[i][j], 0.0f);
#pragma unroll
        for (int ks = 0; ks < 4; ks++) {
            const int kk = ks * 16;
            wmma::fragment<wmma::matrix_a, 16, 16, 16, __half, wmma::row_major> af[2];
            wmma::fragment<wmma::matrix_b, 16, 16, 16, __half, wmma::row_major> bf[2];
#pragma unroll
            for (int i = 0; i < 2; i++)
                wmma::load_matrix_sync(af[i],
                    Ps + (warp_m * 32 + i * 16) * FH_P + kk, FH_P);
#pragma unroll
            for (int j = 0; j < 2; j++)
                wmma::load_matrix_sync(bf[j],
                    Vs + kk * FH_P + warp_n * 32 + j * 16, FH_P);
#pragma unroll
            for (int i = 0; i < 2; i++)
#pragma unroll
                for (int j = 0; j < 2; j++)
                    wmma::mma_sync(oacc[i][j], af[i], bf[j], oacc[i][j]);
        }
        __syncthreads();   // softmax reads of Ss done before overwrite
#pragma unroll
        for (int i = 0; i < 2; i++)
#pragma unroll
            for (int j = 0; j < 2; j++)
                wmma::store_matrix_sync(
                    Ss + (warp_m * 32 + i * 16) * FH_SP + warp_n * 32 + j * 16,
                    oacc[i][j], FH_SP, wmma::mem_row_major);
        __syncthreads();   // PV staged

        // ---- merge ----
        float* rv = Ss + row * FH_SP + cbase;
#pragma unroll
        for (int c = 0; c < 32; c++)
            O[c] = O[c] * alpha + rv[c];
        // next iteration's first sync covers merge-read -> S-store hazard
    }

    float inv = 1.0f / l_run;
    __half* outp = attn + ((size_t)bb * SQ + q0 + row) * 512 + hh * 64 + cbase;
#pragma unroll
    for (int c8 = 0; c8 < 4; c8++) {
        uint2 hv;
        hv.x = h2_u32(__floats2half2_rn(O[c8*8+0] * inv, O[c8*8+1] * inv));
        hv.y = h2_u32(__floats2half2_rn(O[c8*8+2] * inv, O[c8*8+3] * inv));
        uint2 hw;
        hw.x = h2_u32(__floats2half2_rn(O[c8*8+4] * inv, O[c8*8+5] * inv));
        hw.y = h2_u32(__floats2half2_rn(O[c8*8+6] * inv, O[c8*8+7] * inv));
        *(uint2*)(outp + c8 * 8) = hv;
        *(uint2*)(outp + c8 * 8 + 4) = hw;
    }
}

// ---------------- LN(a + b + bias) over D=512; 128 threads/row ---------------
__device__ __forceinline__ void ln_core(float v[4], int tid, const float* g,
                                        const float* be, float4* o4p)
{
    float s1 = v[0] + v[1] + v[2] + v[3];
    float s2 = v[0] * v[0] + v[1] * v[1] + v[2] * v[2] + v[3] * v[3];
#pragma unroll
    for (int o = 16; o; o >>= 1) {
        s1 += __shfl_xor_sync(~0u, s1, o);
        s2 += __shfl_xor_sync(~0u, s2, o);
    }
    __shared__ float sh1[4], sh2[4];
    if ((tid & 31) == 0) { sh1[tid >> 5] = s1; sh2[tid >> 5] = s2; }
    __syncthreads();
    float rs1 = sh1[0] + sh1[1] + sh1[2] + sh1[3];
    float rs2 = sh2[0] + sh2[1] + sh2[2] + sh2[3];
    float mean = rs1 * (1.0f / 512.0f);
    float var = rs2 * (1.0f / 512.0f) - mean * mean;
    float rstd = rsqrtf(var + 1e-5f);
    float4 g4 = *(const float4*)(g + tid * 4);
    float4 b4 = *(const float4*)(be + tid * 4);
    o4p->x = (v[0] - mean) * rstd * g4.x + b4.x;
    o4p->y = (v[1] - mean) * rstd * g4.y + b4.y;
    o4p->z = (v[2] - mean) * rstd * g4.z + b4.z;
    o4p->w = (v[3] - mean) * rstd * g4.w + b4.w;
}

__global__ __launch_bounds__(128)
void ln_add_k(const float* __restrict__ a, const float* __restrict__ bsrc,
              const float* __restrict__ bias,
              const float* __restrict__ g, const float* __restrict__ be,
              float* __restrict__ out)
{
    const size_t base = (size_t)blockIdx.x * DD;
    const int tid = threadIdx.x;
    float4 va = *(const float4*)(a + base + tid * 4);
    float4 vb = *(const float4*)(bsrc + base + tid * 4);
    float4 vc = *(const float4*)(bias + tid * 4);
    float v[4] = {va.x + vb.x + vc.x, va.y + vb.y + vc.y,
                  va.z + vb.z + vc.z, va.w + vb.w + vc.w};
    float4 o4;
    ln_core(v, tid, g, be, &o4);
    *(float4*)(out + base + tid * 4) = o4;
}

// LN(x1 + upsample(a2) + bias) -> fp32 out AND fp16 out
__global__ __launch_bounds__(128)
void ln_interp_dual(const float* __restrict__ x1, const float* __restrict__ a2,
                    const float* __restrict__ bias,
                    const float* __restrict__ g, const float* __restrict__ be,
                    float* __restrict__ out, __half* __restrict__ outh)
{
    const int r = blockIdx.x;
    const int b = r >> 10, i = r & 1023;
    float src = (i + 0.5f) * 0.5f - 0.5f;
    src = fminf(fmaxf(src, 0.0f), (float)(S2 - 1));
    int i0 = (int)floorf(src);
    int i1 = min(i0 + 1, S2 - 1);
    float w = src - (float)i0;

    const size_t base = (size_t)r * DD;
    const size_t b0 = ((size_t)b * S2 + i0) * DD;
    const size_t b1 = ((size_t)b * S2 + i1) * DD;
    const int tid = threadIdx.x;

    float4 vx = *(const float4*)(x1 + base + tid * 4);
    float4 v0 = *(const float4*)(a2 + b0 + tid * 4);
    float4 v1 = *(const float4*)(a2 + b1 + tid * 4);
    float4 vc = *(const float4*)(bias + tid * 4);
    float v[4];
    v[0] = vx.x + v0.x * (1.f - w) + v1.x * w + vc.x;
    v[1] = vx.y + v0.y * (1.f - w) + v1.y * w + vc.y;
    v[2] = vx.z + v0.z * (1.f - w) + v1.z * w + vc.z;
    v[3] = vx.w + v0.w * (1.f - w) + v1.w * w + vc.w;
    float4 o4;
    ln_core(v, tid, g, be, &o4);
    *(float4*)(out + base + tid * 4) = o4;
    uint2 hv;
    hv.x = h2_u32(__floats2half2_rn(o4.x, o4.y));
    hv.y = h2_u32(__floats2half2_rn(o4.z, o4.w));
    *(uint2*)(outh + base + tid * 4) = hv;
}

// avg_pool1d k=2 s=2 -> fp16
__global__ void pool_k(const float* __restrict__ x, __half* __restrict__ out)
{
    size_t idx = ((size_t)blockIdx.x * 256 + threadIdx.x) * 2;
    int d = (int)(idx & 511);
    size_t bt = idx >> 9;
    int t = (int)(bt & (S2 - 1));
    int b = (int)(bt >> 9);
    size_t src = ((size_t)b * SS + 2 * t) * DD + d;
    float2 a = *(const float2*)(x + src);
    float2 c = *(const float2*)(x + src + DD);
    __half2 h = __floats2half2_rn(0.5f * (a.x + c.x), 0.5f * (a.y + c.y));
    *(__half2*)(out + idx) = h;
}

// ---------------- host side ---------------------------------------------------
extern "C" void kernel_launch(void* const* d_in, const int* in_sizes, int n_in,
                              void* d_out, int out_size)
{
    const float* x      = (const float*)d_in[0];
    const float* w_in1  = (const float*)d_in[1];
    const float* b_in1  = (const float*)d_in[2];
    const float* w_out1 = (const float*)d_in[3];
    const float* b_out1 = (const float*)d_in[4];
    const float* w_in2  = (const float*)d_in[5];
    const float* b_in2  = (const float*)d_in[6];
    const float* w_out2 = (const float*)d_in[7];
    const float* b_out2 = (const float*)d_in[8];
    const float* g1     = (const float*)d_in[9];
    const float* beta1  = (const float*)d_in[10];
    const float* g2     = (const float*)d_in[11];
    const float* beta2  = (const float*)d_in[12];
    const float* g3     = (const float*)d_in[13];
    const float* beta3  = (const float*)d_in[14];
    const float* w_ff1  = (const float*)d_in[15];
    const float* b_ff1  = (const float*)d_in[16];
    const float* w_ff2  = (const float*)d_in[17];
    const float* b_ff2  = (const float*)d_in[18];

    __half *qkvh, *attnh, *hh, *xh, *pooledh, *x2h;
    __half *w1h, *wo1h, *w2h, *wo2h, *wf1h, *wf2h;
    float *x1, *a2, *x2, *ff;
    cudaGetSymbolAddress((void**)&qkvh,    g_qkvh);
    cudaGetSymbolAddress((void**)&attnh,   g_attnh);
    cudaGetSymbolAddress((void**)&hh,      g_hh);
    cudaGetSymbolAddress((void**)&xh,      g_xh);
    cudaGetSymbolAddress((void**)&pooledh, g_pooledh);
    cudaGetSymbolAddress((void**)&x2h,     g_x2h);
    cudaGetSymbolAddress((void**)&w1h,     g_w1h);
    cudaGetSymbolAddress((void**)&wo1h,    g_wo1h);
    cudaGetSymbolAddress((void**)&w2h,     g_w2h);
    cudaGetSymbolAddress((void**)&wo2h,    g_wo2h);
    cudaGetSymbolAddress((void**)&wf1h,    g_wf1h);
    cudaGetSymbolAddress((void**)&wf2h,    g_wf2h);
    cudaGetSymbolAddress((void**)&x1,      g_x1);
    cudaGetSymbolAddress((void**)&a2,      g_a2);
    cudaGetSymbolAddress((void**)&x2,      g_x2);
    cudaGetSymbolAddress((void**)&ff,      g_ff);

    cudaFuncSetAttribute(gemm_h<0,0>,
                         cudaFuncAttributeMaxDynamicSharedMemorySize, GE_SMEM);
    cudaFuncSetAttribute(gemm_h<1,1>,
                         cudaFuncAttributeMaxDynamicSharedMemorySize, GE_SMEM);
    cudaFuncSetAttribute(gemm_h<2,1>,
                         cudaFuncAttributeMaxDynamicSharedMemorySize, GE_SMEM);
    cudaFuncSetAttribute(flash_fp16<SS>,
                         cudaFuncAttributeMaxDynamicSharedMemorySize, FH_SMEM);
    cudaFuncSetAttribute(flash_fp16<S2>,
                         cudaFuncAttributeMaxDynamicSharedMemorySize, FH_SMEM);

    const int M1 = BB * SS;   // 8192
    const int M2 = BB * S2;   // 4096

    // ---- weight + input conversion ----
    f2h_k<<<(1536*512)/1024, 256>>>(w_in1, w1h);
    f2h_k<<<(512*512)/1024, 256>>>(w_out1, wo1h);
    f2h_k<<<(1536*512)/1024, 256>>>(w_in2, w2h);
    f2h_k<<<(512*512)/1024, 256>>>(w_out2, wo2h);
    f2h_k<<<(2048*512)/1024, 256>>>(w_ff1, wf1h);
    f2h_k<<<(2048*512)/1024, 256>>>(w_ff2, wf2h);
    f2h_k<<<((size_t)M1*512)/1024, 256>>>(x, xh);

    // ---- MHA 1 ----
    gemm_h<1,1><<<dim3(1536/128, M1/128), 256, GE_SMEM>>>(
        xh, 512, w1h, 512, b_in1, qkvh, 1536, 512);
    flash_fp16<SS><<<dim3(1, SS/128, BB*HH), 256, FH_SMEM>>>(qkvh, attnh);
    gemm_h<0,0><<<dim3(512/128, M1/128), 256, GE_SMEM>>>(
        attnh, 512, wo1h, 512, nullptr, ff, 512, 512);
    ln_add_k<<<M1, 128>>>(x, ff, b_out1, g1, beta1, x1);

    // ---- pool + MHA 2 ----
    pool_k<<<(BB*S2*DD)/512, 256>>>(x1, pooledh);
    gemm_h<1,1><<<dim3(1536/128, M2/128), 256, GE_SMEM>>>(
        pooledh, 512, w2h, 512, b_in2, qkvh, 1536, 512);
    flash_fp16<S2><<<dim3(1, S2/128, BB*HH), 256, FH_SMEM>>>(qkvh, attnh);
    gemm_h<0,0><<<dim3(512/128, M2/128), 256, GE_SMEM>>>(
        attnh, 512, wo2h, 512, nullptr, a2, 512, 512);

    // ---- upsample + residual + LN2 (dual fp32/fp16 out) ----
    ln_interp_dual<<<M1, 128>>>(x1, a2, b_out2, g2, beta2, x2, x2h);

    // ---- FFN ----
    gemm_h<2,1><<<dim3(2048/128, M1/128), 256, GE_SMEM>>>(
        x2h, 512, wf1h, 512, b_ff1, hh, 2048, 512);
    gemm_h<0,0><<<dim3(512/128, M1/128), 256, GE_SMEM>>>(
        hh, 2048, wf2h, 2048, nullptr, ff, 512, 2048);
    ln_add_k<<<M1, 128>>>(x2, ff, b_ff2, g3, beta3, (float*)d_out);
}

// round 17
// speedup vs baseline: 1.4945x; 1.4945x over previous
#include <cuda_runtime.h>
#include <mma.h>
#include <cuda_fp16.h>
#include <math.h>
#include <stdint.h>
#include <string.h>

using namespace nvcuda;

// Problem constants
#define BB 8
#define SS 1024
#define DD 512
#define HH 8
#define HD 64
#define S2 (SS/2)

// ---------------- scratch (static device globals; no cudaMalloc) -------------
__device__ __half g_qkvh [(size_t)BB*SS*3*DD];
__device__ __half g_attnh[(size_t)BB*SS*DD];
__device__ __half g_hh   [(size_t)BB*SS*4*DD];
__device__ __half g_xh   [(size_t)BB*SS*DD];
__device__ __half g_pooledh[(size_t)BB*S2*DD];
__device__ __half g_x2h  [(size_t)BB*SS*DD];
__device__ __half g_w1h  [1536*512];
__device__ __half g_wo1h [512*512];
__device__ __half g_w2h  [1536*512];
__device__ __half g_wo2h [512*512];
__device__ __half g_wf1h [2048*512];
__device__ __half g_wf2h [512*2048];

__device__ float g_x1    [(size_t)BB*SS*DD];
__device__ float g_a2    [(size_t)BB*S2*DD];
__device__ float g_x2    [(size_t)BB*SS*DD];
__device__ float g_ff    [(size_t)BB*SS*DD];

// ---------------- helpers -----------------------------------------------------
__device__ __forceinline__ uint32_t h2_u32(__half2 h)
{
    uint32_t u;
    memcpy(&u, &h, 4);
    return u;
}
__device__ __forceinline__ void cp16h(__half* dst, const __half* src)
{
    unsigned sa = (unsigned)__cvta_generic_to_shared(dst);
    asm volatile("cp.async.cg.shared.global [%0], [%1], 16;\n" :: "r"(sa), "l"(src));
}
__device__ __forceinline__ void cp_commit()
{
    asm volatile("cp.async.commit_group;\n");
}

// ---------------- fp32 -> fp16 conversion ------------------------------------
__global__ void f2h_k(const float* __restrict__ in, __half* __restrict__ out)
{
    size_t i = ((size_t)blockIdx.x * 256 + threadIdx.x) * 4;
    float4 v = *(const float4*)(in + i);
    uint2 hv;
    hv.x = h2_u32(__floats2half2_rn(v.x, v.y));
    hv.y = h2_u32(__floats2half2_rn(v.z, v.w));
    *(uint2*)(out + i) = hv;
}

// =====================================================================
// NT fp16 GEMM: C[m,n] = A[m,k] * B[n,k]  (+bias, opt GELU)
// BK=64 (4 k16 steps/stage), cp.async double-buffered, 128x128 block,
// 8 warps, 2 CTAs/SM.  ACT: 0/1/2.  OUTH: 1 -> fp16 output.
// =====================================================================
#define GE_SMEM 73728
#define HP 72
#define HSTG (2*128*HP)

template<int ACT, int OUTH>
__global__ __launch_bounds__(256, 2)
void gemm_h(const __half* __restrict__ A, int ldA,
            const __half* __restrict__ B, int ldB,
            const float* __restrict__ bias,
            void* __restrict__ Cv, int ldC, int K)
{
    constexpr int BM = 128, BN = 128;
    constexpr int WARPS_M = 2;
    constexpr int TM = 4, TN = 2;
    constexpr int NTH = 256;

    extern __shared__ __align__(128) char smem[];
    __half* hs = (__half*)smem;

    const int tid = threadIdx.x;
    const int wid = tid >> 5;
    const int warp_m = wid % WARPS_M;
    const int warp_n = wid / WARPS_M;
    const int m0 = blockIdx.y * BM;
    const int n0 = blockIdx.x * BN;

    wmma::fragment<wmma::accumulator, 16, 16, 16, float> acc[TM][TN];
#pragma unroll
    for (int i = 0; i < TM; i++)
#pragma unroll
        for (int j = 0; j < TN; j++) wmma::fill_fragment(acc[i][j], 0.0f);

    const int nt = K >> 6;

    auto load_stage = [&](int st, int k0) {
        __half* as = hs + st * HSTG;
        __half* bs = as + 128 * HP;
#pragma unroll
        for (int q = 0; q < 4; q++) {
            int ch = tid + q * NTH;
            int r = ch >> 3;
            int c = (ch & 7) * 8;
            cp16h(as + r * HP + c, A + (size_t)(m0 + r) * ldA + k0 + c);
        }
#pragma unroll
        for (int q = 0; q < 4; q++) {
            int ch = tid + q * NTH;
            int r = ch >> 3;
            int c = (ch & 7) * 8;
            cp16h(bs + r * HP + c, B + (size_t)(n0 + r) * ldB + k0 + c);
        }
        cp_commit();
    };

    load_stage(0, 0);

    for (int it = 0; it < nt; it++) {
        const int cur = it & 1;
        if (it + 1 < nt) {
            load_stage(cur ^ 1, (it + 1) << 6);
            asm volatile("cp.async.wait_group 1;\n");
        } else {
            asm volatile("cp.async.wait_group 0;\n");
        }
        __syncthreads();

        const __half* as = hs + cur * HSTG;
        const __half* bs = as + 128 * HP;
#pragma unroll
        for (int ks = 0; ks < 4; ks++) {
            const int kk = ks * 16;
            wmma::fragment<wmma::matrix_a, 16, 16, 16, __half, wmma::row_major> af[TM];
            wmma::fragment<wmma::matrix_b, 16, 16, 16, __half, wmma::col_major> bf[TN];
#pragma unroll
            for (int i = 0; i < TM; i++)
                wmma::load_matrix_sync(af[i],
                    as + (warp_m * TM * 16 + i * 16) * HP + kk, HP);
#pragma unroll
            for (int j = 0; j < TN; j++)
                wmma::load_matrix_sync(bf[j],
                    bs + (warp_n * TN * 16 + j * 16) * HP + kk, HP);
#pragma unroll
            for (int i = 0; i < TM; i++)
#pragma unroll
                for (int j = 0; j < TN; j++)
                    wmma::mma_sync(acc[i][j], af[i], bf[j], acc[i][j]);
        }
        __syncthreads();
    }

    constexpr int CSTR = BN + 4;
    float* St = (float*)smem;
#pragma unroll
    for (int i = 0; i < TM; i++)
#pragma unroll
        for (int j = 0; j < TN; j++)
            wmma::store_matrix_sync(
                St + (warp_m * TM * 16 + i * 16) * CSTR + warp_n * TN * 16 + j * 16,
                acc[i][j], CSTR, wmma::mem_row_major);
    __syncthreads();

#pragma unroll
    for (int idx = tid; idx < BM * BN / 4; idx += NTH) {
        int r = idx >> 5;
        int c = (idx & 31) * 4;
        float4 v = *(float4*)&St[r * CSTR + c];
        if (ACT >= 1) {
            float4 bv = *(const float4*)&bias[n0 + c];
            v.x += bv.x; v.y += bv.y; v.z += bv.z; v.w += bv.w;
        }
        if (ACT == 2) {
            v.x = 0.5f * v.x * (1.0f + erff(v.x * 0.70710678118654752f));
            v.y = 0.5f * v.y * (1.0f + erff(v.y * 0.70710678118654752f));
            v.z = 0.5f * v.z * (1.0f + erff(v.z * 0.70710678118654752f));
            v.w = 0.5f * v.w * (1.0f + erff(v.w * 0.70710678118654752f));
        }
        if (OUTH) {
            __half* Ch = (__half*)Cv;
            uint2 hv;
            hv.x = h2_u32(__floats2half2_rn(v.x, v.y));
            hv.y = h2_u32(__floats2half2_rn(v.z, v.w));
            *(uint2*)&Ch[(size_t)(m0 + r) * ldC + n0 + c] = hv;
        } else {
            float* Cf = (float*)Cv;
            *(float4*)&Cf[(size_t)(m0 + r) * ldC + n0 + c] = v;
        }
    }
}

// =====================================================================
// Flash attention fp16 (EXACT R15 config): BQ=128, single KV buffer,
// fp16 Q/K/V/P + fp32 softmax/O, fp16 out. __launch_bounds__(256), no clamp.
// =====================================================================
#define FH_P 72
#define FH_SP 68
#define FH_SMEM ((128*FH_P + 64*FH_P + 64*FH_P + 128*FH_P) * 2 + 128*FH_SP*4)

template<int SQ>
__global__ __launch_bounds__(256)
void flash_fp16(const __half* __restrict__ qkv, __half* __restrict__ attn)
{
    extern __shared__ __align__(128) char smem[];
    __half* Qs = (__half*)smem;
    __half* Ks = Qs + 128 * FH_P;
    __half* Vs = Ks + 64 * FH_P;
    __half* Ps = Vs + 64 * FH_P;
    float*  Ss = (float*)(Ps + 128 * FH_P);

    const int z = blockIdx.z;
    const int bb = z >> 3, hh = z & 7;
    const int q0 = blockIdx.y * 128;
    const __half* Qg = qkv + (size_t)bb * SQ * 1536 + hh * 64;
    const __half* Kg = Qg + 512;
    const __half* Vg = Qg + 1024;

    const int tid = threadIdx.x;
    const int wid = tid >> 5;
    const int warp_m = wid & 3;
    const int warp_n = wid >> 2;

    const int row = tid >> 1;
    const int cbase = (tid & 1) * 32;

#pragma unroll
    for (int i = tid; i < 128 * 8; i += 256) {
        int r = i >> 3;
        int c = (i & 7) * 8;
        cp16h(Qs + r * FH_P + c, Qg + (size_t)(q0 + r) * 1536 + c);
    }
    cp_commit();

    float m_run = -1e30f, l_run = 0.0f;
    float O[32];
#pragma unroll
    for (int c = 0; c < 32; c++) O[c] = 0.0f;

    const int NT = SQ / 64;
    for (int kt = 0; kt < NT; kt++) {
#pragma unroll
        for (int i = tid; i < 64 * 8; i += 256) {
            int r = i >> 3;
            int c = (i & 7) * 8;
            cp16h(Ks + r * FH_P + c, Kg + (size_t)(kt * 64 + r) * 1536 + c);
            cp16h(Vs + r * FH_P + c, Vg + (size_t)(kt * 64 + r) * 1536 + c);
        }
        cp_commit();
        asm volatile("cp.async.wait_group 0;\n");
        __syncthreads();

        wmma::fragment<wmma::accumulator, 16, 16, 16, float> sacc[2][2];
#pragma unroll
        for (int i = 0; i < 2; i++)
#pragma unroll
            for (int j = 0; j < 2; j++) wmma::fill_fragment(sacc[i][j], 0.0f);
#pragma unroll
        for (int ks = 0; ks < 4; ks++) {
            const int kk = ks * 16;
            wmma::fragment<wmma::matrix_a, 16, 16, 16, __half, wmma::row_major> af[2];
            wmma::fragment<wmma::matrix_b, 16, 16, 16, __half, wmma::col_major> bf[2];
#pragma unroll
            for (int i = 0; i < 2; i++)
                wmma::load_matrix_sync(af[i],
                    Qs + (warp_m * 32 + i * 16) * FH_P + kk, FH_P);
#pragma unroll
            for (int j = 0; j < 2; j++)
                wmma::load_matrix_sync(bf[j],
                    Ks + (warp_n * 32 + j * 16) * FH_P + kk, FH_P);
#pragma unroll
            for (int i = 0; i < 2; i++)
#pragma unroll
                for (int j = 0; j < 2; j++)
                    wmma::mma_sync(sacc[i][j], af[i], bf[j], sacc[i][j]);
        }
#pragma unroll
        for (int i = 0; i < 2; i++)
#pragma unroll
            for (int j = 0; j < 2; j++) {
#pragma unroll
                for (int t = 0; t < sacc[i][j].num_elements; t++)
                    sacc[i][j].x[t] *= 0.125f;
                wmma::store_matrix_sync(
                    Ss + (warp_m * 32 + i * 16) * FH_SP + warp_n * 32 + j * 16,
                    sacc[i][j], FH_SP, wmma::mem_row_major);
            }
        __syncthreads();

        float* rp = Ss + row * FH_SP + cbase;
        __half* pp = Ps + row * FH_P + cbase;
        float mx = -1e30f;
#pragma unroll
        for (int c = 0; c < 32; c++) mx = fmaxf(mx, rp[c]);
        mx = fmaxf(mx, __shfl_xor_sync(~0u, mx, 1));
        float m_new = fmaxf(m_run, mx);
        float alpha = __expf(m_run - m_new);
        float sum = 0.0f;
#pragma unroll
        for (int c = 0; c < 32; c += 2) {
            float p0 = __expf(rp[c + 0] - m_new);
            float p1 = __expf(rp[c + 1] - m_new);
            sum += p0 + p1;
            *(__half2*)(pp + c) = __floats2half2_rn(p0, p1);
        }
        sum += __shfl_xor_sync(~0u, sum, 1);
        l_run = l_run * alpha + sum;
        m_run = m_new;
        __syncthreads();

        wmma::fragment<wmma::accumulator, 16, 16, 16, float> oacc[2][2];
#pragma unroll
        for (int i = 0; i < 2; i++)
#pragma unroll
            for (int j = 0; j < 2; j++) wmma::fill_fragment(oacc[i][j], 0.0f);
#pragma unroll
        for (int ks = 0; ks < 4; ks++) {
            const int kk = ks * 16;
            wmma::fragment<wmma::matrix_a, 16, 16, 16, __half, wmma::row_major> af[2];
            wmma::fragment<wmma::matrix_b, 16, 16, 16, __half, wmma::row_major> bf[2];
#pragma unroll
            for (int i = 0; i < 2; i++)
                wmma::load_matrix_sync(af[i],
                    Ps + (warp_m * 32 + i * 16) * FH_P + kk, FH_P);
#pragma unroll
            for (int j = 0; j < 2; j++)
                wmma::load_matrix_sync(bf[j],
                    Vs + kk * FH_P + warp_n * 32 + j * 16, FH_P);
#pragma unroll
            for (int i = 0; i < 2; i++)
#pragma unroll
                for (int j = 0; j < 2; j++)
                    wmma::mma_sync(oacc[i][j], af[i], bf[j], oacc[i][j]);
        }
        __syncthreads();
#pragma unroll
        for (int i = 0; i < 2; i++)
#pragma unroll
            for (int j = 0; j < 2; j++)
                wmma::store_matrix_sync(
                    Ss + (warp_m * 32 + i * 16) * FH_SP + warp_n * 32 + j * 16,
                    oacc[i][j], FH_SP, wmma::mem_row_major);
        __syncthreads();

        float* rv = Ss + row * FH_SP + cbase;
#pragma unroll
        for (int c = 0; c < 32; c++)
            O[c] = O[c] * alpha + rv[c];
    }

    float inv = 1.0f / l_run;
    __half* outp = attn + ((size_t)bb * SQ + q0 + row) * 512 + hh * 64 + cbase;
#pragma unroll
    for (int c8 = 0; c8 < 4; c8++) {
        uint2 hv;
        hv.x = h2_u32(__floats2half2_rn(O[c8*8+0] * inv, O[c8*8+1] * inv));
        hv.y = h2_u32(__floats2half2_rn(O[c8*8+2] * inv, O[c8*8+3] * inv));
        uint2 hw;
        hw.x = h2_u32(__floats2half2_rn(O[c8*8+4] * inv, O[c8*8+5] * inv));
        hw.y = h2_u32(__floats2half2_rn(O[c8*8+6] * inv, O[c8*8+7] * inv));
        *(uint2*)(outp + c8 * 8) = hv;
        *(uint2*)(outp + c8 * 8 + 4) = hw;
    }
}

// ---------------- LN(a + b + bias) over D=512; 128 threads/row ---------------
__device__ __forceinline__ void ln_core(float v[4], int tid, const float* g,
                                        const float* be, float4* o4p)
{
    float s1 = v[0] + v[1] + v[2] + v[3];
    float s2 = v[0] * v[0] + v[1] * v[1] + v[2] * v[2] + v[3] * v[3];
#pragma unroll
    for (int o = 16; o; o >>= 1) {
        s1 += __shfl_xor_sync(~0u, s1, o);
        s2 += __shfl_xor_sync(~0u, s2, o);
    }
    __shared__ float sh1[4], sh2[4];
    if ((tid & 31) == 0) { sh1[tid >> 5] = s1; sh2[tid >> 5] = s2; }
    __syncthreads();
    float rs1 = sh1[0] + sh1[1] + sh1[2] + sh1[3];
    float rs2 = sh2[0] + sh2[1] + sh2[2] + sh2[3];
    float mean = rs1 * (1.0f / 512.0f);
    float var = rs2 * (1.0f / 512.0f) - mean * mean;
    float rstd = rsqrtf(var + 1e-5f);
    float4 g4 = *(const float4*)(g + tid * 4);
    float4 b4 = *(const float4*)(be + tid * 4);
    o4p->x = (v[0] - mean) * rstd * g4.x + b4.x;
    o4p->y = (v[1] - mean) * rstd * g4.y + b4.y;
    o4p->z = (v[2] - mean) * rstd * g4.z + b4.z;
    o4p->w = (v[3] - mean) * rstd * g4.w + b4.w;
}

__global__ __launch_bounds__(128)
void ln_add_k(const float* __restrict__ a, const float* __restrict__ bsrc,
              const float* __restrict__ bias,
              const float* __restrict__ g, const float* __restrict__ be,
              float* __restrict__ out)
{
    const size_t base = (size_t)blockIdx.x * DD;
    const int tid = threadIdx.x;
    float4 va = *(const float4*)(a + base + tid * 4);
    float4 vb = *(const float4*)(bsrc + base + tid * 4);
    float4 vc = *(const float4*)(bias + tid * 4);
    float v[4] = {va.x + vb.x + vc.x, va.y + vb.y + vc.y,
                  va.z + vb.z + vc.z, va.w + vb.w + vc.w};
    float4 o4;
    ln_core(v, tid, g, be, &o4);
    *(float4*)(out + base + tid * 4) = o4;
}

// LN(x1 + upsample(a2) + bias) -> fp32 out AND fp16 out
__global__ __launch_bounds__(128)
void ln_interp_dual(const float* __restrict__ x1, const float* __restrict__ a2,
                    const float* __restrict__ bias,
                    const float* __restrict__ g, const float* __restrict__ be,
                    float* __restrict__ out, __half* __restrict__ outh)
{
    const int r = blockIdx.x;
    const int b = r >> 10, i = r & 1023;
    float src = (i + 0.5f) * 0.5f - 0.5f;
    src = fminf(fmaxf(src, 0.0f), (float)(S2 - 1));
    int i0 = (int)floorf(src);
    int i1 = min(i0 + 1, S2 - 1);
    float w = src - (float)i0;

    const size_t base = (size_t)r * DD;
    const size_t b0 = ((size_t)b * S2 + i0) * DD;
    const size_t b1 = ((size_t)b * S2 + i1) * DD;
    const int tid = threadIdx.x;

    float4 vx = *(const float4*)(x1 + base + tid * 4);
    float4 v0 = *(const float4*)(a2 + b0 + tid * 4);
    float4 v1 = *(const float4*)(a2 + b1 + tid * 4);
    float4 vc = *(const float4*)(bias + tid * 4);
    float v[4];
    v[0] = vx.x + v0.x * (1.f - w) + v1.x * w + vc.x;
    v[1] = vx.y + v0.y * (1.f - w) + v1.y * w + vc.y;
    v[2] = vx.z + v0.z * (1.f - w) + v1.z * w + vc.z;
    v[3] = vx.w + v0.w * (1.f - w) + v1.w * w + vc.w;
    float4 o4;
    ln_core(v, tid, g, be, &o4);
    *(float4*)(out + base + tid * 4) = o4;
    uint2 hv;
    hv.x = h2_u32(__floats2half2_rn(o4.x, o4.y));
    hv.y = h2_u32(__floats2half2_rn(o4.z, o4.w));
    *(uint2*)(outh + base + tid * 4) = hv;
}

// avg_pool1d k=2 s=2 -> fp16
__global__ void pool_k(const float* __restrict__ x, __half* __restrict__ out)
{
    size_t idx = ((size_t)blockIdx.x * 256 + threadIdx.x) * 2;
    int d = (int)(idx & 511);
    size_t bt = idx >> 9;
    int t = (int)(bt & (S2 - 1));
    int b = (int)(bt >> 9);
    size_t src = ((size_t)b * SS + 2 * t) * DD + d;
    float2 a = *(const float2*)(x + src);
    float2 c = *(const float2*)(x + src + DD);
    __half2 h = __floats2half2_rn(0.5f * (a.x + c.x), 0.5f * (a.y + c.y));
    *(__half2*)(out + idx) = h;
}

// ---------------- host side ---------------------------------------------------
extern "C" void kernel_launch(void* const* d_in, const int* in_sizes, int n_in,
                              void* d_out, int out_size)
{
    const float* x      = (const float*)d_in[0];
    const float* w_in1  = (const float*)d_in[1];
    const float* b_in1  = (const float*)d_in[2];
    const float* w_out1 = (const float*)d_in[3];
    const float* b_out1 = (const float*)d_in[4];
    const float* w_in2  = (const float*)d_in[5];
    const float* b_in2  = (const float*)d_in[6];
    const float* w_out2 = (const float*)d_in[7];
    const float* b_out2 = (const float*)d_in[8];
    const float* g1     = (const float*)d_in[9];
    const float* beta1  = (const float*)d_in[10];
    const float* g2     = (const float*)d_in[11];
    const float* beta2  = (const float*)d_in[12];
    const float* g3     = (const float*)d_in[13];
    const float* beta3  = (const float*)d_in[14];
    const float* w_ff1  = (const float*)d_in[15];
    const float* b_ff1  = (const float*)d_in[16];
    const float* w_ff2  = (const float*)d_in[17];
    const float* b_ff2  = (const float*)d_in[18];

    __half *qkvh, *attnh, *hh, *xh, *pooledh, *x2h;
    __half *w1h, *wo1h, *w2h, *wo2h, *wf1h, *wf2h;
    float *x1, *a2, *x2, *ff;
    cudaGetSymbolAddress((void**)&qkvh,    g_qkvh);
    cudaGetSymbolAddress((void**)&attnh,   g_attnh);
    cudaGetSymbolAddress((void**)&hh,      g_hh);
    cudaGetSymbolAddress((void**)&xh,      g_xh);
    cudaGetSymbolAddress((void**)&pooledh, g_pooledh);
    cudaGetSymbolAddress((void**)&x2h,     g_x2h);
    cudaGetSymbolAddress((void**)&w1h,     g_w1h);
    cudaGetSymbolAddress((void**)&wo1h,    g_wo1h);
    cudaGetSymbolAddress((void**)&w2h,     g_w2h);
    cudaGetSymbolAddress((void**)&wo2h,    g_wo2h);
    cudaGetSymbolAddress((void**)&wf1h,    g_wf1h);
    cudaGetSymbolAddress((void**)&wf2h,    g_wf2h);
    cudaGetSymbolAddress((void**)&x1,      g_x1);
    cudaGetSymbolAddress((void**)&a2,      g_a2);
    cudaGetSymbolAddress((void**)&x2,      g_x2);
    cudaGetSymbolAddress((void**)&ff,      g_ff);

    cudaFuncSetAttribute(gemm_h<0,0>,
                         cudaFuncAttributeMaxDynamicSharedMemorySize, GE_SMEM);
    cudaFuncSetAttribute(gemm_h<1,1>,
                         cudaFuncAttributeMaxDynamicSharedMemorySize, GE_SMEM);
    cudaFuncSetAttribute(gemm_h<2,1>,
                         cudaFuncAttributeMaxDynamicSharedMemorySize, GE_SMEM);
    cudaFuncSetAttribute(flash_fp16<SS>,
                         cudaFuncAttributeMaxDynamicSharedMemorySize, FH_SMEM);
    cudaFuncSetAttribute(flash_fp16<S2>,
                         cudaFuncAttributeMaxDynamicSharedMemorySize, FH_SMEM);

    const int M1 = BB * SS;   // 8192
    const int M2 = BB * S2;   // 4096

    // ---- weight + input conversion ----
    f2h_k<<<(1536*512)/1024, 256>>>(w_in1, w1h);
    f2h_k<<<(512*512)/1024, 256>>>(w_out1, wo1h);
    f2h_k<<<(1536*512)/1024, 256>>>(w_in2, w2h);
    f2h_k<<<(512*512)/1024, 256>>>(w_out2, wo2h);
    f2h_k<<<(2048*512)/1024, 256>>>(w_ff1, wf1h);
    f2h_k<<<(2048*512)/1024, 256>>>(w_ff2, wf2h);
    f2h_k<<<((size_t)M1*512)/1024, 256>>>(x, xh);

    // ---- MHA 1 ----
    gemm_h<1,1><<<dim3(1536/128, M1/128), 256, GE_SMEM>>>(
        xh, 512, w1h, 512, b_in1, qkvh, 1536, 512);
    flash_fp16<SS><<<dim3(1, SS/128, BB*HH), 256, FH_SMEM>>>(qkvh, attnh);
    gemm_h<0,0><<<dim3(512/128, M1/128), 256, GE_SMEM>>>(
        attnh, 512, wo1h, 512, nullptr, ff, 512, 512);
    ln_add_k<<<M1, 128>>>(x, ff, b_out1, g1, beta1, x1);

    // ---- pool + MHA 2 ----
    pool_k<<<(BB*S2*DD)/512, 256>>>(x1, pooledh);
    gemm_h<1,1><<<dim3(1536/128, M2/128), 256, GE_SMEM>>>(
        pooledh, 512, w2h, 512, b_in2, qkvh, 1536, 512);
    flash_fp16<S2><<<dim3(1, S2/128, BB*HH), 256, FH_SMEM>>>(qkvh, attnh);
    gemm_h<0,0><<<dim3(512/128, M2/128), 256, GE_SMEM>>>(
        attnh, 512, wo2h, 512, nullptr, a2, 512, 512);

    // ---- upsample + residual + LN2 (dual fp32/fp16 out) ----
    ln_interp_dual<<<M1, 128>>>(x1, a2, b_out2, g2, beta2, x2, x2h);

    // ---- FFN ----
    gemm_h<2,1><<<dim3(2048/128, M1/128), 256, GE_SMEM>>>(
        x2h, 512, wf1h, 512, b_ff1, hh, 2048, 512);
    gemm_h<0,0><<<dim3(512/128, M1/128), 256, GE_SMEM>>>(
        hh, 2048, wf2h, 2048, nullptr, ff, 512, 2048);
    ln_add_k<<<M1, 128>>>(x2, ff, b_ff2, g3, beta3, (float*)d_out);
}